// round 12
// baseline (speedup 1.0000x reference)
#include <cuda_runtime.h>
#include <cstdint>

#define B_  32
#define N_  1024
#define K_  12
#define H_  64
#define BN_ (B_ * N_)        // 32768 nodes
#define ME_ (BN_ * K_)       // 393216 edges

// ---------------- scratch (static; no cudaMalloc) --------------------------
__device__ float g_dist[(size_t)B_ * N_ * N_];   // 128 MB (CIN=64 layers only)
__device__ int   g_idx[ME_];
__device__ float g_d2[BN_];
__device__ float g_R[(size_t)BN_ * H_];          // P - Q + b1
__device__ float g_Q[(size_t)BN_ * H_];
__device__ float g_f0[(size_t)BN_ * H_];
__device__ float g_f1[(size_t)BN_ * H_];
__device__ float g_sum[H_];                      // zero-init; finalize restores 0
__device__ float g_sqs[H_];
__device__ float g_scale[H_];
__device__ float g_shift[H_];
__device__ float g_pool[B_ * H_];

__device__ __forceinline__ float f4c(const float4& v, int i) {
    return i == 0 ? v.x : i == 1 ? v.y : i == 2 ? v.z : v.w;
}

// ---------------- squared norms --------------------------------------------
template<int CIN>
__global__ void d2_kernel(const float* __restrict__ F) {
    int w    = (blockIdx.x * blockDim.x + threadIdx.x) >> 5;
    int lane = threadIdx.x & 31;
    const float* row = F + (size_t)w * CIN;
    float s = 0.f;
    for (int c = lane; c < CIN; c += 32) { float v = row[c]; s = fmaf(v, v, s); }
    #pragma unroll
    for (int o = 16; o; o >>= 1) s += __shfl_down_sync(0xffffffffu, s, o);
    if (lane == 0) g_d2[w] = s;
}

// ---------------- pairwise distances, CIN=64, SYMMETRIC tile pairs ----------
__global__ __launch_bounds__(256) void dist64_kernel(const float* __restrict__ F) {
    __shared__ __align__(16) float Xi[128][36];
    __shared__ __align__(16) float Xj[128][36];
    __shared__ float d2i[128], d2j[128];

    int tx = threadIdx.x & 15, ty = threadIdx.x >> 4;
    int t  = threadIdx.x;
    int b  = blockIdx.z;

    // pair id -> (ti, tj), ti <= tj
    int p = blockIdx.x;
    int ti = 0;
    while (p >= 8 - ti) { p -= 8 - ti; ++ti; }
    int tj = ti + p;

    int i0 = ti * 128, j0 = tj * 128;
    const float* Fb = F + (size_t)b * (N_ * 64);

    if (t < 128) { d2i[t] = g_d2[b * N_ + i0 + t]; d2j[t] = g_d2[b * N_ + j0 + t]; }

    float acc[8][8];
    #pragma unroll
    for (int m = 0; m < 8; ++m)
        #pragma unroll
        for (int n = 0; n < 8; ++n) acc[m][n] = 0.f;

    for (int c0 = 0; c0 < 64; c0 += 32) {
        __syncthreads();
        for (int i = t; i < 128 * 32; i += 256) {
            int r = i >> 5, k = i & 31;
            Xi[r][k] = Fb[(size_t)(i0 + r) * 64 + c0 + k];
            Xj[r][k] = Fb[(size_t)(j0 + r) * 64 + c0 + k];
        }
        __syncthreads();
        #pragma unroll
        for (int k = 0; k < 32; k += 4) {
            float4 b4[8];
            #pragma unroll
            for (int n = 0; n < 8; ++n)
                b4[n] = *(const float4*)&Xj[tx + 16 * n][k];
            #pragma unroll
            for (int m = 0; m < 8; ++m) {
                float4 a4 = *(const float4*)&Xi[ty * 8 + m][k];
                #pragma unroll
                for (int kk = 0; kk < 4; ++kk) {
                    float av = f4c(a4, kk);
                    #pragma unroll
                    for (int n = 0; n < 8; ++n)
                        acc[m][n] = fmaf(av, f4c(b4[n], kk), acc[m][n]);
                }
            }
        }
    }

    // direct tile: rows i, cols j
    float* D = g_dist + ((size_t)b * N_ + i0) * N_ + j0;
    #pragma unroll
    for (int m = 0; m < 8; ++m) {
        int r = ty * 8 + m;
        float di = d2i[r];
        #pragma unroll
        for (int n = 0; n < 8; ++n)
            D[(size_t)r * N_ + tx + 16 * n] = di + d2j[tx + 16 * n] - 2.0f * acc[m][n];
    }

    // mirrored tile: rows j, cols i (bit-identical values)
    if (ti != tj) {
        float* DT = g_dist + ((size_t)b * N_ + j0) * N_ + i0;
        #pragma unroll
        for (int n = 0; n < 8; ++n) {
            int jr = tx + 16 * n;
            float dj = d2j[jr];
            float4 o0, o1;
            o0.x = dj + d2i[ty * 8 + 0] - 2.0f * acc[0][n];
            o0.y = dj + d2i[ty * 8 + 1] - 2.0f * acc[1][n];
            o0.z = dj + d2i[ty * 8 + 2] - 2.0f * acc[2][n];
            o0.w = dj + d2i[ty * 8 + 3] - 2.0f * acc[3][n];
            o1.x = dj + d2i[ty * 8 + 4] - 2.0f * acc[4][n];
            o1.y = dj + d2i[ty * 8 + 5] - 2.0f * acc[5][n];
            o1.z = dj + d2i[ty * 8 + 6] - 2.0f * acc[6][n];
            o1.w = dj + d2i[ty * 8 + 7] - 2.0f * acc[7][n];
            *(float4*)&DT[(size_t)jr * N_ + ty * 8]     = o0;
            *(float4*)&DT[(size_t)jr * N_ + ty * 8 + 4] = o1;
        }
    }
}

// ---------------- top-K machinery ------------------------------------------
__device__ __forceinline__ unsigned fkey(float d) {
    unsigned u = __float_as_uint(d);
    return u ^ (((unsigned)((int)u >> 31)) | 0x80000000u);
}

__device__ __forceinline__ void ins12(unsigned* lst, unsigned k) {
    if (k < lst[11]) {
        unsigned cur = k;
        #pragma unroll
        for (int s = 0; s < 12; ++s) {
            unsigned lo = min(lst[s], cur);
            cur = max(lst[s], cur);
            lst[s] = lo;
        }
    }
}

__device__ __forceinline__ unsigned warp_thresh12(unsigned* lst, int lane) {
    unsigned T = 0;
    #pragma unroll 1
    for (int r = 0; r < 12; ++r) {
        unsigned w = __reduce_min_sync(0xffffffffu, lst[0]);
        unsigned mask = __ballot_sync(0xffffffffu, lst[0] == w);
        if (lane == __ffs(mask) - 1) {
            #pragma unroll
            for (int s = 0; s < 11; ++s) lst[s] = lst[s + 1];
            lst[11] = 0xFFFFFFFFu;
        }
        T = w;
    }
    return T;
}

// Exact 12th-smallest of the warp's 32 keys-per-lane using the order-stat
// bound: m12 (12th smallest of the 32 per-lane minima) >= T12. Candidates
// (keys <= m12, expected ~15, guaranteed >= 12) are compacted to smem and the
// exact T12 extracted. Fallback to insertion sort if pool overflows (ties).
__device__ __forceinline__ unsigned warp_t12(const unsigned* keys, unsigned kmin,
                                             int lane, unsigned* candw) {
    unsigned m12 = 0;
    {
        unsigned v = kmin;
        #pragma unroll 1
        for (int r = 0; r < 12; ++r) {
            unsigned wv = __reduce_min_sync(0xffffffffu, v);
            m12 = wv;
            unsigned msk = __ballot_sync(0xffffffffu, v == wv);
            if (lane == __ffs(msk) - 1) v = 0xFFFFFFFFu;
        }
    }

    int nc = 0;
    #pragma unroll
    for (int p = 0; p < 32; ++p) nc += (keys[p] <= m12);
    int inc = nc;
    #pragma unroll
    for (int o = 1; o < 32; o <<= 1) {
        int y = __shfl_up_sync(0xffffffffu, inc, o);
        if (lane >= o) inc += y;
    }
    int C   = __shfl_sync(0xffffffffu, inc, 31);
    int off = inc - nc;

    unsigned T = 0;
    if (C <= 64) {
        #pragma unroll
        for (int p = 0; p < 32; ++p)
            if (keys[p] <= m12) candw[off++] = keys[p];
        __syncwarp();
        unsigned v1 = (lane      < C) ? candw[lane]      : 0xFFFFFFFFu;
        unsigned v2 = (lane + 32 < C) ? candw[lane + 32] : 0xFFFFFFFFu;
        #pragma unroll 1
        for (int r = 0; r < 12; ++r) {
            unsigned mv = __reduce_min_sync(0xffffffffu, min(v1, v2));
            T = mv;
            unsigned m1 = __ballot_sync(0xffffffffu, v1 == mv);
            if (m1) {
                if (lane == __ffs(m1) - 1) v1 = 0xFFFFFFFFu;
            } else {
                unsigned m2 = __ballot_sync(0xffffffffu, v2 == mv);
                if (lane == __ffs(m2) - 1) v2 = 0xFFFFFFFFu;
            }
        }
    } else {
        unsigned lst[12];
        #pragma unroll
        for (int i = 0; i < 12; ++i) lst[i] = 0xFFFFFFFFu;
        #pragma unroll
        for (int p = 0; p < 32; ++p) ins12(lst, keys[p]);
        T = warp_thresh12(lst, lane);
    }
    return T;
}

// MODE 0: p=(it*4+c), j=(p>>2)*128 + lane*4 + (p&3)   (float4 strided rows)
// MODE 1: p=it,        j=p*32 + lane
template<int MODE>
__device__ __forceinline__ int map_j(int p, int lane) {
    return (MODE == 0) ? ((p >> 2) * 128 + lane * 4 + (p & 3)) : (p * 32 + lane);
}

// From per-lane less/equal masks, write the exact top-12 index set to sidx[12].
template<int MODE>
__device__ __forceinline__ void select12(unsigned lessm, unsigned eqm,
                                         int lane, int* sidx) {
    int lcnt = __popc(lessm);
    int inc = lcnt;
    #pragma unroll
    for (int o = 1; o < 32; o <<= 1) {
        int y = __shfl_up_sync(0xffffffffu, inc, o);
        if (lane >= o) inc += y;
    }
    int total_less = __shfl_sync(0xffffffffu, inc, 31);   // <= 11
    int r = inc - lcnt;
    unsigned m = lessm;
    while (m) {
        int p = __ffs(m) - 1; m &= m - 1;
        sidx[r++] = map_j<MODE>(p, lane);
    }
    int need = 12 - total_less;
    #pragma unroll 1
    for (int f = 0; f < need; ++f) {
        int jc = eqm ? map_j<MODE>(__ffs(eqm) - 1, lane) : 0x7FFFFFFF;
        int jw = __reduce_min_sync(0xffffffffu, jc);
        if (jc == jw) eqm &= eqm - 1;     // j unique across (p,lane): one lane pops
        if (lane == 0) sidx[total_less + f] = jw;
    }
}

// BN stats: accumulate sum/sumsq of h1 = R[i]+Q[j] for this row's 12 edges.
__device__ __forceinline__ void stats_epilogue(int gi, int gbase, int keep, int lane,
                                               float* ssum, float* ssqs) {
    int h = lane * 2;
    float2 r2 = *(const float2*)&g_R[(size_t)gi * 64 + h];
    float s0 = 0.f, s1 = 0.f, q0 = 0.f, q1 = 0.f;
    #pragma unroll
    for (int k = 0; k < 12; ++k) {
        int j = gbase + __shfl_sync(0xffffffffu, keep, k);
        float2 qv = *(const float2*)&g_Q[(size_t)j * 64 + h];
        float v0 = r2.x + qv.x, v1 = r2.y + qv.y;
        s0 += v0; s1 += v1;
        q0 = fmaf(v0, v0, q0); q1 = fmaf(v1, v1, q1);
    }
    atomicAdd(&ssum[h],     s0);
    atomicAdd(&ssum[h + 1], s1);
    atomicAdd(&ssqs[h],     q0);
    atomicAdd(&ssqs[h + 1], q1);
}

// ---------------- top-K for CIN=64 layers (reads g_dist) + fused BN stats --
__global__ __launch_bounds__(256) void topk64_kernel() {
    __shared__ float ssum[64], ssqs[64];
    __shared__ int   sidx[8][12];
    __shared__ unsigned cand[8][64];
    int t = threadIdx.x;
    if (t < 64) { ssum[t] = 0.f; ssqs[t] = 0.f; }
    __syncthreads();

    int w = t >> 5, lane = t & 31;
    int row = blockIdx.x * 8 + w;
    const float* dr = g_dist + (size_t)row * N_;

    unsigned keys[32];
    unsigned kmin = 0xFFFFFFFFu;
    #pragma unroll
    for (int it = 0; it < 8; ++it) {
        float4 dv = *(const float4*)(dr + it * 128 + lane * 4);
        keys[it * 4 + 0] = fkey(dv.x);
        keys[it * 4 + 1] = fkey(dv.y);
        keys[it * 4 + 2] = fkey(dv.z);
        keys[it * 4 + 3] = fkey(dv.w);
        kmin = min(kmin, min(min(keys[it * 4], keys[it * 4 + 1]),
                             min(keys[it * 4 + 2], keys[it * 4 + 3])));
    }

    unsigned T = warp_t12(keys, kmin, lane, cand[w]);

    unsigned lessm = 0, eqm = 0;
    #pragma unroll
    for (int p = 0; p < 32; ++p) {
        lessm |= (unsigned)(keys[p] < T)  << p;
        eqm   |= (unsigned)(keys[p] == T) << p;
    }
    select12<0>(lessm, eqm, lane, sidx[w]);
    __syncwarp();

    int keep = sidx[w][lane < 12 ? lane : 0];
    if (lane < 12) g_idx[row * 12 + lane] = keep;
    stats_epilogue(row, (row >> 10) << 10, keep, lane, ssum, ssqs);
    __syncthreads();
    if (t < 64) { atomicAdd(&g_sum[t], ssum[t]); atomicAdd(&g_sqs[t], ssqs[t]); }
}

// ---------------- fused dist+top-K for layer 0 (CIN=3) + BN stats ----------
__global__ __launch_bounds__(256) void topk3_kernel(const float* __restrict__ x) {
    __shared__ float xs[3072];
    __shared__ float sd2[1024];
    __shared__ float ssum[64], ssqs[64];
    __shared__ int   sidx[8][12];
    __shared__ unsigned cand[8][64];

    int t = threadIdx.x;
    int b = blockIdx.x >> 7;
    int rbase = (blockIdx.x & 127) * 8;
    const float* xb = x + b * 3072;

    for (int i = t; i < 3072; i += 256) xs[i] = xb[i];
    for (int i = t; i < 1024; i += 256) sd2[i] = g_d2[b * 1024 + i];
    if (t < 64) { ssum[t] = 0.f; ssqs[t] = 0.f; }
    __syncthreads();

    int w = t >> 5, lane = t & 31;
    int il = rbase + w;
    float xi0 = xs[il * 3], xi1 = xs[il * 3 + 1], xi2 = xs[il * 3 + 2];
    float d2iv = sd2[il];

    unsigned keys[32];
    unsigned kmin = 0xFFFFFFFFu;
    #pragma unroll
    for (int it = 0; it < 32; ++it) {
        int j = it * 32 + lane;
        float a = fmaf(xi0, xs[j * 3], 0.f);
        a = fmaf(xi1, xs[j * 3 + 1], a);
        a = fmaf(xi2, xs[j * 3 + 2], a);
        float d = d2iv + sd2[j] - 2.0f * a;
        keys[it] = fkey(d);
        kmin = min(kmin, keys[it]);
    }

    unsigned T = warp_t12(keys, kmin, lane, cand[w]);

    unsigned lessm = 0, eqm = 0;
    #pragma unroll
    for (int it = 0; it < 32; ++it) {
        lessm |= (unsigned)(keys[it] < T)  << it;
        eqm   |= (unsigned)(keys[it] == T) << it;
    }
    select12<1>(lessm, eqm, lane, sidx[w]);
    __syncwarp();

    int gi = b * 1024 + il;
    int keep = sidx[w][lane < 12 ? lane : 0];
    if (lane < 12) g_idx[gi * 12 + lane] = keep;
    stats_epilogue(gi, b << 10, keep, lane, ssum, ssqs);
    __syncthreads();
    if (t < 64) { atomicAdd(&g_sum[t], ssum[t]); atomicAdd(&g_sqs[t], ssqs[t]); }
}

// ---------------- node-level MLP1 decomposition ----------------------------
__global__ __launch_bounds__(256) void pq64_kernel(const float* __restrict__ F,
                                                   const float* __restrict__ W1,
                                                   const float* __restrict__ b1) {
    __shared__ __align__(16) float Xs[128][36];
    __shared__ __align__(16) float Wt[128][36];
    int tx = threadIdx.x & 15, ty = threadIdx.x >> 4;
    int t  = threadIdx.x;
    int n0 = blockIdx.x * 128;

    float acc[8][8];
    #pragma unroll
    for (int m = 0; m < 8; ++m)
        #pragma unroll
        for (int n = 0; n < 8; ++n) acc[m][n] = 0.f;

    for (int c0 = 0; c0 < 64; c0 += 32) {
        __syncthreads();
        for (int i = t; i < 128 * 32; i += 256) {
            int r = i >> 5, k = i & 31;
            Xs[r][k] = F[(size_t)(n0 + r) * 64 + c0 + k];
            Wt[r][k] = W1[(c0 + k + ((r >> 6) << 6)) * 64 + (r & 63)];
        }
        __syncthreads();
        #pragma unroll
        for (int k = 0; k < 32; k += 4) {
            float4 b4[8];
            #pragma unroll
            for (int n = 0; n < 8; ++n)
                b4[n] = *(const float4*)&Wt[tx + 16 * n][k];
            #pragma unroll
            for (int m = 0; m < 8; ++m) {
                float4 a4 = *(const float4*)&Xs[ty * 8 + m][k];
                #pragma unroll
                for (int kk = 0; kk < 4; ++kk) {
                    float av = f4c(a4, kk);
                    #pragma unroll
                    for (int n = 0; n < 8; ++n)
                        acc[m][n] = fmaf(av, f4c(b4[n], kk), acc[m][n]);
                }
            }
        }
    }

    #pragma unroll
    for (int m = 0; m < 8; ++m) {
        size_t node = n0 + ty * 8 + m;
        #pragma unroll
        for (int n = 0; n < 4; ++n) {
            int h = tx + 16 * n;
            float P = acc[m][n], Q = acc[m][n + 4];
            g_R[node * 64 + h] = P - Q + b1[h];
            g_Q[node * 64 + h] = Q;
        }
    }
}

__global__ void pq3_kernel(const float* __restrict__ x,
                           const float* __restrict__ W1,
                           const float* __restrict__ b1) {
    int gid = blockIdx.x * 256 + threadIdx.x;    // node*64 + h
    int node = gid >> 6, h = gid & 63;
    const float* xr = x + node * 3;
    float x0 = xr[0], x1 = xr[1], x2 = xr[2];
    float P = fmaf(x0, W1[h],       fmaf(x1, W1[64 + h],  x2 * W1[128 + h]));
    float Q = fmaf(x0, W1[192 + h], fmaf(x1, W1[256 + h], x2 * W1[320 + h]));
    g_R[gid] = P - Q + b1[h];
    g_Q[gid] = Q;
}

// ---------------- BN stats finalize (also resets accumulators) -------------
__global__ void finalize_stats(const float* __restrict__ g, const float* __restrict__ be) {
    int h = threadIdx.x;
    const float invM = 1.f / (float)ME_;
    float m = g_sum[h] * invM;
    float v = g_sqs[h] * invM - m * m;
    float sc = g[h] * rsqrtf(v + 1e-5f);
    g_scale[h] = sc;
    g_shift[h] = fmaf(-m, sc, be[h]);
    g_sum[h] = 0.f;     // restore zeros for next layer / next replay
    g_sqs[h] = 0.f;
}

// ---------------- BN + ReLU + mean over K + W2 GEMM ------------------------
__global__ __launch_bounds__(256) void bn_mlp2_kernel(float* __restrict__ Fout,
                                                      const float* __restrict__ W2,
                                                      const float* __restrict__ b2) {
    __shared__ float As[64][65];
    __shared__ float Ws[64][65];
    int t  = threadIdx.x;
    int n0 = blockIdx.x * 64;

    for (int i = t; i < 64 * 64; i += 256) Ws[i >> 6][i & 63] = W2[i];

    {
        int nloc = t >> 2;
        int node = n0 + nloc;
        int hq   = (t & 3) * 16;
        float R[16], sc[16], sh[16], a[16];
        #pragma unroll
        for (int p = 0; p < 4; ++p) {
            *(float4*)&R[p * 4]  = *(const float4*)&g_R[(size_t)node * 64 + hq + p * 4];
            *(float4*)&sc[p * 4] = *(const float4*)&g_scale[hq + p * 4];
            *(float4*)&sh[p * 4] = *(const float4*)&g_shift[hq + p * 4];
        }
        #pragma unroll
        for (int r = 0; r < 16; ++r) a[r] = 0.f;

        const int* ip = g_idx + node * 12;
        int base = (node >> 10) << 10;
        #pragma unroll 1
        for (int k = 0; k < 12; ++k) {
            int j = base + ip[k];
            const float4* Qp = (const float4*)&g_Q[(size_t)j * 64 + hq];
            float qv[16];
            #pragma unroll
            for (int p = 0; p < 4; ++p) *(float4*)&qv[p * 4] = Qp[p];
            #pragma unroll
            for (int r = 0; r < 16; ++r)
                a[r] += fmaxf(fmaf(sc[r], R[r] + qv[r], sh[r]), 0.f);
        }
        #pragma unroll
        for (int r = 0; r < 16; ++r) As[hq + r][nloc] = a[r] * (1.f / 12.f);
    }
    __syncthreads();

    int tx = t & 15, ty = t >> 4;
    float acc[4][4];
    #pragma unroll
    for (int m = 0; m < 4; ++m)
        #pragma unroll
        for (int n = 0; n < 4; ++n) acc[m][n] = 0.f;

    #pragma unroll
    for (int h = 0; h < 64; ++h) {
        float a[4], bv[4];
        #pragma unroll
        for (int m = 0; m < 4; ++m) a[m] = As[h][ty * 4 + m];
        #pragma unroll
        for (int n = 0; n < 4; ++n) bv[n] = Ws[h][tx + 16 * n];
        #pragma unroll
        for (int m = 0; m < 4; ++m)
            #pragma unroll
            for (int n = 0; n < 4; ++n) acc[m][n] = fmaf(a[m], bv[n], acc[m][n]);
    }

    #pragma unroll
    for (int n = 0; n < 4; ++n) {
        int o = tx + 16 * n;
        float bo = b2[o];
        #pragma unroll
        for (int m = 0; m < 4; ++m)
            Fout[(size_t)(n0 + ty * 4 + m) * 64 + o] = acc[m][n] + bo;
    }
}

// ---------------- global mean pool over nodes ------------------------------
__global__ void pool_kernel(const float* __restrict__ F) {
    __shared__ float red[4][64];
    int t = threadIdx.x;
    int h = t & 63, s = t >> 6;
    int b = blockIdx.x;
    float acc = 0.f;
    for (int n = s; n < N_; n += 4)
        acc += F[((size_t)b * N_ + n) * H_ + h];
    red[s][h] = acc;
    __syncthreads();
    if (t < 64)
        g_pool[b * H_ + t] = (red[0][t] + red[1][t] + red[2][t] + red[3][t]) * (1.f / N_);
}

// ---------------- FC head ---------------------------------------------------
__global__ void fc_kernel(const float* __restrict__ wf1, const float* __restrict__ bf1,
                          const float* __restrict__ gf,  const float* __restrict__ bef,
                          const float* __restrict__ wf2, const float* __restrict__ bf2,
                          float* __restrict__ out) {
    __shared__ float zs[32][33];
    __shared__ float sc[32], sh[32];
    int t = threadIdx.x;
    int b = t >> 5, j = t & 31;

    float acc = bf1[j];
    #pragma unroll
    for (int h = 0; h < 64; ++h)
        acc = fmaf(g_pool[b * 64 + h], wf1[h * 32 + j], acc);
    zs[b][j] = acc;
    __syncthreads();

    if (t < 32) {
        float s = 0.f;
        for (int q = 0; q < 32; ++q) s += zs[q][t];
        float m = s * (1.f / 32.f);
        float v = 0.f;
        for (int q = 0; q < 32; ++q) { float d = zs[q][t] - m; v = fmaf(d, d, v); }
        v *= (1.f / 32.f);
        float s2 = gf[t] * rsqrtf(v + 1e-5f);
        sc[t] = s2;
        sh[t] = fmaf(-m, s2, bef[t]);
    }
    __syncthreads();

    float r = fmaxf(fmaf(zs[b][j], sc[j], sh[j]), 0.f);
    zs[b][j] = r;
    __syncthreads();

    if (t < 64) {
        int q = t >> 1, o = t & 1;
        float a = bf2[o];
        #pragma unroll
        for (int jj = 0; jj < 32; ++jj)
            a = fmaf(zs[q][jj], wf2[jj * 2 + o], a);
        out[q * 2 + o] = a;
    }
}

// ---------------- host ------------------------------------------------------
static void run_layer64(const float* Fin, float* Fout,
                        const float* W1, const float* b1,
                        const float* g, const float* be,
                        const float* W2, const float* b2) {
    d2_kernel<64><<<4096, 256>>>(Fin);
    dist64_kernel<<<dim3(36, 1, 32), 256>>>(Fin);
    pq64_kernel<<<256, 256>>>(Fin, W1, b1);
    topk64_kernel<<<4096, 256>>>();
    finalize_stats<<<1, 64>>>(g, be);
    bn_mlp2_kernel<<<512, 256>>>(Fout, W2, b2);
}

extern "C" void kernel_launch(void* const* d_in, const int* in_sizes, int n_in,
                              void* d_out, int out_size) {
    const float* x   = (const float*)d_in[0];
    const float* w0a = (const float*)d_in[1];
    const float* b0a = (const float*)d_in[2];
    const float* g0  = (const float*)d_in[3];
    const float* be0 = (const float*)d_in[4];
    const float* w0b = (const float*)d_in[5];
    const float* b0b = (const float*)d_in[6];
    const float* wa  = (const float*)d_in[7];
    const float* ba  = (const float*)d_in[8];
    const float* ga  = (const float*)d_in[9];
    const float* bea = (const float*)d_in[10];
    const float* wb  = (const float*)d_in[11];
    const float* bb  = (const float*)d_in[12];
    const float* wf1 = (const float*)d_in[13];
    const float* bf1 = (const float*)d_in[14];
    const float* gf  = (const float*)d_in[15];
    const float* bef = (const float*)d_in[16];
    const float* wf2 = (const float*)d_in[17];
    const float* bf2 = (const float*)d_in[18];
    float* out = (float*)d_out;

    float *f0 = nullptr, *f1 = nullptr;
    cudaGetSymbolAddress((void**)&f0, g_f0);
    cudaGetSymbolAddress((void**)&f1, g_f1);

    // ---- layer 0 (CIN=3): fused dist+topk, no g_dist traffic ----
    d2_kernel<3><<<4096, 256>>>(x);
    pq3_kernel<<<8192, 256>>>(x, w0a, b0a);
    topk3_kernel<<<4096, 256>>>(x);
    finalize_stats<<<1, 64>>>(g0, be0);
    bn_mlp2_kernel<<<512, 256>>>(f0, w0b, b0b);

    // ---- layers 1..3 (CIN=64) ----
    run_layer64(f0, f1, wa,            ba,       ga,       bea,       wb,            bb);
    run_layer64(f1, f0, wa + 128 * 64, ba + 64,  ga + 64,  bea + 64,  wb + 64 * 64,  bb + 64);
    run_layer64(f0, f1, wa + 256 * 64, ba + 128, ga + 128, bea + 128, wb + 128 * 64, bb + 128);

    pool_kernel<<<32, 256>>>(f1);
    fc_kernel<<<1, 1024>>>(wf1, bf1, gf, bef, wf2, bf2, out);
}

// round 14
// speedup vs baseline: 1.4437x; 1.4437x over previous
#include <cuda_runtime.h>
#include <cstdint>

#define B_  32
#define N_  1024
#define K_  12
#define H_  64
#define BN_ (B_ * N_)        // 32768 nodes
#define ME_ (BN_ * K_)       // 393216 edges

// ---------------- scratch (static; no cudaMalloc) --------------------------
__device__ float g_dist[(size_t)B_ * N_ * N_];   // 128 MB (CIN=64 layers only)
__device__ int   g_idx[ME_];
__device__ float g_d2[BN_];
__device__ float g_R[(size_t)BN_ * H_];          // P - Q + b1
__device__ float g_Q[(size_t)BN_ * H_];
__device__ float g_f0[(size_t)BN_ * H_];
__device__ float g_f1[(size_t)BN_ * H_];
__device__ float g_sum[4 * H_];                  // per-layer; zero-init; fc restores 0
__device__ float g_sqs[4 * H_];
__device__ float g_pool[B_ * H_];

__device__ __forceinline__ float f4c(const float4& v, int i) {
    return i == 0 ? v.x : i == 1 ? v.y : i == 2 ? v.z : v.w;
}

// ---------------- squared norms --------------------------------------------
template<int CIN>
__global__ void d2_kernel(const float* __restrict__ F) {
    int w    = (blockIdx.x * blockDim.x + threadIdx.x) >> 5;
    int lane = threadIdx.x & 31;
    const float* row = F + (size_t)w * CIN;
    float s = 0.f;
    for (int c = lane; c < CIN; c += 32) { float v = row[c]; s = fmaf(v, v, s); }
    #pragma unroll
    for (int o = 16; o; o >>= 1) s += __shfl_down_sync(0xffffffffu, s, o);
    if (lane == 0) g_d2[w] = s;
}

// ---------------- pairwise distances, CIN=64, SYMMETRIC tile pairs ----------
__global__ __launch_bounds__(256) void dist64_kernel(const float* __restrict__ F) {
    __shared__ __align__(16) float Xi[128][36];
    __shared__ __align__(16) float Xj[128][36];
    __shared__ float d2i[128], d2j[128];

    int tx = threadIdx.x & 15, ty = threadIdx.x >> 4;
    int t  = threadIdx.x;
    int b  = blockIdx.z;

    // pair id -> (ti, tj), ti <= tj
    int p = blockIdx.x;
    int ti = 0;
    while (p >= 8 - ti) { p -= 8 - ti; ++ti; }
    int tj = ti + p;

    int i0 = ti * 128, j0 = tj * 128;
    const float* Fb = F + (size_t)b * (N_ * 64);

    if (t < 128) { d2i[t] = g_d2[b * N_ + i0 + t]; d2j[t] = g_d2[b * N_ + j0 + t]; }

    float acc[8][8];
    #pragma unroll
    for (int m = 0; m < 8; ++m)
        #pragma unroll
        for (int n = 0; n < 8; ++n) acc[m][n] = 0.f;

    for (int c0 = 0; c0 < 64; c0 += 32) {
        __syncthreads();
        for (int i = t; i < 128 * 32; i += 256) {
            int r = i >> 5, k = i & 31;
            Xi[r][k] = Fb[(size_t)(i0 + r) * 64 + c0 + k];
            Xj[r][k] = Fb[(size_t)(j0 + r) * 64 + c0 + k];
        }
        __syncthreads();
        #pragma unroll
        for (int k = 0; k < 32; k += 4) {
            float4 b4[8];
            #pragma unroll
            for (int n = 0; n < 8; ++n)
                b4[n] = *(const float4*)&Xj[tx + 16 * n][k];
            #pragma unroll
            for (int m = 0; m < 8; ++m) {
                float4 a4 = *(const float4*)&Xi[ty * 8 + m][k];
                #pragma unroll
                for (int kk = 0; kk < 4; ++kk) {
                    float av = f4c(a4, kk);
                    #pragma unroll
                    for (int n = 0; n < 8; ++n)
                        acc[m][n] = fmaf(av, f4c(b4[n], kk), acc[m][n]);
                }
            }
        }
    }

    // direct tile: rows i, cols j
    float* D = g_dist + ((size_t)b * N_ + i0) * N_ + j0;
    #pragma unroll
    for (int m = 0; m < 8; ++m) {
        int r = ty * 8 + m;
        float di = d2i[r];
        #pragma unroll
        for (int n = 0; n < 8; ++n)
            D[(size_t)r * N_ + tx + 16 * n] = di + d2j[tx + 16 * n] - 2.0f * acc[m][n];
    }

    // mirrored tile: rows j, cols i (bit-identical values)
    if (ti != tj) {
        float* DT = g_dist + ((size_t)b * N_ + j0) * N_ + i0;
        #pragma unroll
        for (int n = 0; n < 8; ++n) {
            int jr = tx + 16 * n;
            float dj = d2j[jr];
            float4 o0, o1;
            o0.x = dj + d2i[ty * 8 + 0] - 2.0f * acc[0][n];
            o0.y = dj + d2i[ty * 8 + 1] - 2.0f * acc[1][n];
            o0.z = dj + d2i[ty * 8 + 2] - 2.0f * acc[2][n];
            o0.w = dj + d2i[ty * 8 + 3] - 2.0f * acc[3][n];
            o1.x = dj + d2i[ty * 8 + 4] - 2.0f * acc[4][n];
            o1.y = dj + d2i[ty * 8 + 5] - 2.0f * acc[5][n];
            o1.z = dj + d2i[ty * 8 + 6] - 2.0f * acc[6][n];
            o1.w = dj + d2i[ty * 8 + 7] - 2.0f * acc[7][n];
            *(float4*)&DT[(size_t)jr * N_ + ty * 8]     = o0;
            *(float4*)&DT[(size_t)jr * N_ + ty * 8 + 4] = o1;
        }
    }
}

// ---------------- top-K machinery (round-11 proven: shfl butterflies) -------
__device__ __forceinline__ unsigned fkey(float d) {
    unsigned u = __float_as_uint(d);
    return u ^ (((unsigned)((int)u >> 31)) | 0x80000000u);
}

__device__ __forceinline__ void ins12(unsigned* lst, unsigned k) {
    if (k < lst[11]) {
        unsigned cur = k;
        #pragma unroll
        for (int s = 0; s < 12; ++s) {
            unsigned lo = min(lst[s], cur);
            cur = max(lst[s], cur);
            lst[s] = lo;
        }
    }
}

__device__ __forceinline__ unsigned warp_thresh12(unsigned* lst, int lane) {
    unsigned T = 0;
    #pragma unroll 1
    for (int r = 0; r < 12; ++r) {
        unsigned w = lst[0];
        #pragma unroll
        for (int o = 16; o; o >>= 1) w = min(w, __shfl_xor_sync(0xffffffffu, w, o));
        unsigned mask = __ballot_sync(0xffffffffu, lst[0] == w);
        if (lane == __ffs(mask) - 1) {
            #pragma unroll
            for (int s = 0; s < 11; ++s) lst[s] = lst[s + 1];
            lst[11] = 0xFFFFFFFFu;
        }
        T = w;
    }
    return T;
}

// Exact 12th-smallest of the warp's 32 keys-per-lane using the order-stat
// bound: m12 (12th smallest of the 32 per-lane minima) >= T12.
__device__ __forceinline__ unsigned warp_t12(const unsigned* keys, unsigned kmin,
                                             int lane, unsigned* candw) {
    unsigned m12 = 0;
    {
        unsigned v = kmin;
        #pragma unroll 1
        for (int r = 0; r < 12; ++r) {
            unsigned wv = v;
            #pragma unroll
            for (int o = 16; o; o >>= 1) wv = min(wv, __shfl_xor_sync(0xffffffffu, wv, o));
            m12 = wv;
            unsigned msk = __ballot_sync(0xffffffffu, v == wv);
            if (lane == __ffs(msk) - 1) v = 0xFFFFFFFFu;
        }
    }

    int nc = 0;
    #pragma unroll
    for (int p = 0; p < 32; ++p) nc += (keys[p] <= m12);
    int inc = nc;
    #pragma unroll
    for (int o = 1; o < 32; o <<= 1) {
        int y = __shfl_up_sync(0xffffffffu, inc, o);
        if (lane >= o) inc += y;
    }
    int C   = __shfl_sync(0xffffffffu, inc, 31);
    int off = inc - nc;

    unsigned T = 0;
    if (C <= 64) {
        #pragma unroll
        for (int p = 0; p < 32; ++p)
            if (keys[p] <= m12) candw[off++] = keys[p];
        __syncwarp();
        unsigned v1 = (lane      < C) ? candw[lane]      : 0xFFFFFFFFu;
        unsigned v2 = (lane + 32 < C) ? candw[lane + 32] : 0xFFFFFFFFu;
        #pragma unroll 1
        for (int r = 0; r < 12; ++r) {
            unsigned mv = min(v1, v2);
            #pragma unroll
            for (int o = 16; o; o >>= 1) mv = min(mv, __shfl_xor_sync(0xffffffffu, mv, o));
            T = mv;
            unsigned m1 = __ballot_sync(0xffffffffu, v1 == mv);
            if (m1) {
                if (lane == __ffs(m1) - 1) v1 = 0xFFFFFFFFu;
            } else {
                unsigned m2 = __ballot_sync(0xffffffffu, v2 == mv);
                if (lane == __ffs(m2) - 1) v2 = 0xFFFFFFFFu;
            }
        }
    } else {
        unsigned lst[12];
        #pragma unroll
        for (int i = 0; i < 12; ++i) lst[i] = 0xFFFFFFFFu;
        #pragma unroll
        for (int p = 0; p < 32; ++p) ins12(lst, keys[p]);
        T = warp_thresh12(lst, lane);
    }
    return T;
}

// MODE 0: p=(it*4+c), j=(p>>2)*128 + lane*4 + (p&3)   (float4 strided rows)
// MODE 1: p=it,        j=p*32 + lane
template<int MODE>
__device__ __forceinline__ int map_j(int p, int lane) {
    return (MODE == 0) ? ((p >> 2) * 128 + lane * 4 + (p & 3)) : (p * 32 + lane);
}

// From per-lane less/equal masks, write the exact top-12 index set to sidx[12].
template<int MODE>
__device__ __forceinline__ void select12(unsigned lessm, unsigned eqm,
                                         int lane, int* sidx) {
    int lcnt = __popc(lessm);
    int inc = lcnt;
    #pragma unroll
    for (int o = 1; o < 32; o <<= 1) {
        int y = __shfl_up_sync(0xffffffffu, inc, o);
        if (lane >= o) inc += y;
    }
    int total_less = __shfl_sync(0xffffffffu, inc, 31);   // <= 11
    int r = inc - lcnt;
    unsigned m = lessm;
    while (m) {
        int p = __ffs(m) - 1; m &= m - 1;
        sidx[r++] = map_j<MODE>(p, lane);
    }
    int need = 12 - total_less;
    #pragma unroll 1
    for (int f = 0; f < need; ++f) {
        int jc = eqm ? map_j<MODE>(__ffs(eqm) - 1, lane) : 0x7FFFFFFF;
        int jw = jc;
        #pragma unroll
        for (int o = 16; o; o >>= 1) jw = min(jw, __shfl_xor_sync(0xffffffffu, jw, o));
        if (jc == jw) eqm &= eqm - 1;     // j unique across (p,lane): one lane pops
        if (lane == 0) sidx[total_less + f] = jw;
    }
}

// BN stats: accumulate sum/sumsq of h1 = R[i]+Q[j] for this row's 12 edges.
__device__ __forceinline__ void stats_epilogue(int gi, int gbase, int keep, int lane,
                                               float* ssum, float* ssqs) {
    int h = lane * 2;
    float2 r2 = *(const float2*)&g_R[(size_t)gi * 64 + h];
    float s0 = 0.f, s1 = 0.f, q0 = 0.f, q1 = 0.f;
    #pragma unroll
    for (int k = 0; k < 12; ++k) {
        int j = gbase + __shfl_sync(0xffffffffu, keep, k);
        float2 qv = *(const float2*)&g_Q[(size_t)j * 64 + h];
        float v0 = r2.x + qv.x, v1 = r2.y + qv.y;
        s0 += v0; s1 += v1;
        q0 = fmaf(v0, v0, q0); q1 = fmaf(v1, v1, q1);
    }
    atomicAdd(&ssum[h],     s0);
    atomicAdd(&ssum[h + 1], s1);
    atomicAdd(&ssqs[h],     q0);
    atomicAdd(&ssqs[h + 1], q1);
}

// ---------------- top-K for CIN=64 layers (reads g_dist) + fused BN stats --
__global__ __launch_bounds__(256) void topk64_kernel(int L) {
    __shared__ float ssum[64], ssqs[64];
    __shared__ int   sidx[8][12];
    __shared__ unsigned cand[8][64];
    int t = threadIdx.x;
    if (t < 64) { ssum[t] = 0.f; ssqs[t] = 0.f; }
    __syncthreads();

    int w = t >> 5, lane = t & 31;
    int row = blockIdx.x * 8 + w;
    const float* dr = g_dist + (size_t)row * N_;

    unsigned keys[32];
    unsigned kmin = 0xFFFFFFFFu;
    #pragma unroll
    for (int it = 0; it < 8; ++it) {
        float4 dv = *(const float4*)(dr + it * 128 + lane * 4);
        keys[it * 4 + 0] = fkey(dv.x);
        keys[it * 4 + 1] = fkey(dv.y);
        keys[it * 4 + 2] = fkey(dv.z);
        keys[it * 4 + 3] = fkey(dv.w);
        kmin = min(kmin, min(min(keys[it * 4], keys[it * 4 + 1]),
                             min(keys[it * 4 + 2], keys[it * 4 + 3])));
    }

    unsigned T = warp_t12(keys, kmin, lane, cand[w]);

    unsigned lessm = 0, eqm = 0;
    #pragma unroll
    for (int p = 0; p < 32; ++p) {
        lessm |= (unsigned)(keys[p] < T)  << p;
        eqm   |= (unsigned)(keys[p] == T) << p;
    }
    select12<0>(lessm, eqm, lane, sidx[w]);
    __syncwarp();

    int keep = sidx[w][lane < 12 ? lane : 0];
    if (lane < 12) g_idx[row * 12 + lane] = keep;
    stats_epilogue(row, (row >> 10) << 10, keep, lane, ssum, ssqs);
    __syncthreads();
    if (t < 64) { atomicAdd(&g_sum[L * 64 + t], ssum[t]); atomicAdd(&g_sqs[L * 64 + t], ssqs[t]); }
}

// ---------------- fused dist+top-K for layer 0 (CIN=3) + BN stats ----------
__global__ __launch_bounds__(256) void topk3_kernel(const float* __restrict__ x) {
    __shared__ float xs[3072];
    __shared__ float sd2[1024];
    __shared__ float ssum[64], ssqs[64];
    __shared__ int   sidx[8][12];
    __shared__ unsigned cand[8][64];

    int t = threadIdx.x;
    int b = blockIdx.x >> 7;
    int rbase = (blockIdx.x & 127) * 8;
    const float* xb = x + b * 3072;

    for (int i = t; i < 3072; i += 256) xs[i] = xb[i];
    for (int i = t; i < 1024; i += 256) sd2[i] = g_d2[b * 1024 + i];
    if (t < 64) { ssum[t] = 0.f; ssqs[t] = 0.f; }
    __syncthreads();

    int w = t >> 5, lane = t & 31;
    int il = rbase + w;
    float xi0 = xs[il * 3], xi1 = xs[il * 3 + 1], xi2 = xs[il * 3 + 2];
    float d2iv = sd2[il];

    unsigned keys[32];
    unsigned kmin = 0xFFFFFFFFu;
    #pragma unroll
    for (int it = 0; it < 32; ++it) {
        int j = it * 32 + lane;
        float a = fmaf(xi0, xs[j * 3], 0.f);
        a = fmaf(xi1, xs[j * 3 + 1], a);
        a = fmaf(xi2, xs[j * 3 + 2], a);
        float d = d2iv + sd2[j] - 2.0f * a;
        keys[it] = fkey(d);
        kmin = min(kmin, keys[it]);
    }

    unsigned T = warp_t12(keys, kmin, lane, cand[w]);

    unsigned lessm = 0, eqm = 0;
    #pragma unroll
    for (int it = 0; it < 32; ++it) {
        lessm |= (unsigned)(keys[it] < T)  << it;
        eqm   |= (unsigned)(keys[it] == T) << it;
    }
    select12<1>(lessm, eqm, lane, sidx[w]);
    __syncwarp();

    int gi = b * 1024 + il;
    int keep = sidx[w][lane < 12 ? lane : 0];
    if (lane < 12) g_idx[gi * 12 + lane] = keep;
    stats_epilogue(gi, b << 10, keep, lane, ssum, ssqs);
    __syncthreads();
    if (t < 64) { atomicAdd(&g_sum[t], ssum[t]); atomicAdd(&g_sqs[t], ssqs[t]); }
}

// ---------------- node-level MLP1 decomposition ----------------------------
__global__ __launch_bounds__(256) void pq64_kernel(const float* __restrict__ F,
                                                   const float* __restrict__ W1,
                                                   const float* __restrict__ b1) {
    __shared__ __align__(16) float Xs[128][36];
    __shared__ __align__(16) float Wt[128][36];
    int tx = threadIdx.x & 15, ty = threadIdx.x >> 4;
    int t  = threadIdx.x;
    int n0 = blockIdx.x * 128;

    float acc[8][8];
    #pragma unroll
    for (int m = 0; m < 8; ++m)
        #pragma unroll
        for (int n = 0; n < 8; ++n) acc[m][n] = 0.f;

    for (int c0 = 0; c0 < 64; c0 += 32) {
        __syncthreads();
        for (int i = t; i < 128 * 32; i += 256) {
            int r = i >> 5, k = i & 31;
            Xs[r][k] = F[(size_t)(n0 + r) * 64 + c0 + k];
            Wt[r][k] = W1[(c0 + k + ((r >> 6) << 6)) * 64 + (r & 63)];
        }
        __syncthreads();
        #pragma unroll
        for (int k = 0; k < 32; k += 4) {
            float4 b4[8];
            #pragma unroll
            for (int n = 0; n < 8; ++n)
                b4[n] = *(const float4*)&Wt[tx + 16 * n][k];
            #pragma unroll
            for (int m = 0; m < 8; ++m) {
                float4 a4 = *(const float4*)&Xs[ty * 8 + m][k];
                #pragma unroll
                for (int kk = 0; kk < 4; ++kk) {
                    float av = f4c(a4, kk);
                    #pragma unroll
                    for (int n = 0; n < 8; ++n)
                        acc[m][n] = fmaf(av, f4c(b4[n], kk), acc[m][n]);
                }
            }
        }
    }

    #pragma unroll
    for (int m = 0; m < 8; ++m) {
        size_t node = n0 + ty * 8 + m;
        #pragma unroll
        for (int n = 0; n < 4; ++n) {
            int h = tx + 16 * n;
            float P = acc[m][n], Q = acc[m][n + 4];
            g_R[node * 64 + h] = P - Q + b1[h];
            g_Q[node * 64 + h] = Q;
        }
    }
}

__global__ void pq3_kernel(const float* __restrict__ x,
                           const float* __restrict__ W1,
                           const float* __restrict__ b1) {
    int gid = blockIdx.x * 256 + threadIdx.x;    // node*64 + h
    int node = gid >> 6, h = gid & 63;
    const float* xr = x + node * 3;
    float x0 = xr[0], x1 = xr[1], x2 = xr[2];
    float P = fmaf(x0, W1[h],       fmaf(x1, W1[64 + h],  x2 * W1[128 + h]));
    float Q = fmaf(x0, W1[192 + h], fmaf(x1, W1[256 + h], x2 * W1[320 + h]));
    g_R[gid] = P - Q + b1[h];
    g_Q[gid] = Q;
}

// ---------------- BN(scale/shift in-block) + ReLU + mean-K + W2 GEMM -------
__global__ __launch_bounds__(256) void bn_mlp2_kernel(float* __restrict__ Fout,
                                                      const float* __restrict__ W2,
                                                      const float* __restrict__ b2,
                                                      const float* __restrict__ g,
                                                      const float* __restrict__ be,
                                                      int L) {
    __shared__ float As[64][65];
    __shared__ float Ws[64][65];
    __shared__ float ssc[64], ssh[64];
    int t  = threadIdx.x;
    int n0 = blockIdx.x * 64;

    if (t < 64) {
        const float invM = 1.f / (float)ME_;
        float m = g_sum[L * 64 + t] * invM;
        float v = g_sqs[L * 64 + t] * invM - m * m;
        float sc = g[t] * rsqrtf(v + 1e-5f);
        ssc[t] = sc;
        ssh[t] = fmaf(-m, sc, be[t]);
    }
    for (int i = t; i < 64 * 64; i += 256) Ws[i >> 6][i & 63] = W2[i];
    __syncthreads();

    {
        int nloc = t >> 2;
        int node = n0 + nloc;
        int hq   = (t & 3) * 16;
        float R[16], sc[16], sh[16], a[16];
        #pragma unroll
        for (int p = 0; p < 4; ++p)
            *(float4*)&R[p * 4] = *(const float4*)&g_R[(size_t)node * 64 + hq + p * 4];
        #pragma unroll
        for (int r = 0; r < 16; ++r) { sc[r] = ssc[hq + r]; sh[r] = ssh[hq + r]; a[r] = 0.f; }

        const int* ip = g_idx + node * 12;
        int base = (node >> 10) << 10;
        #pragma unroll 1
        for (int k = 0; k < 12; ++k) {
            int j = base + ip[k];
            const float4* Qp = (const float4*)&g_Q[(size_t)j * 64 + hq];
            float qv[16];
            #pragma unroll
            for (int p = 0; p < 4; ++p) *(float4*)&qv[p * 4] = Qp[p];
            #pragma unroll
            for (int r = 0; r < 16; ++r)
                a[r] += fmaxf(fmaf(sc[r], R[r] + qv[r], sh[r]), 0.f);
        }
        #pragma unroll
        for (int r = 0; r < 16; ++r) As[hq + r][nloc] = a[r] * (1.f / 12.f);
    }
    __syncthreads();

    int tx = t & 15, ty = t >> 4;
    float acc[4][4];
    #pragma unroll
    for (int m = 0; m < 4; ++m)
        #pragma unroll
        for (int n = 0; n < 4; ++n) acc[m][n] = 0.f;

    #pragma unroll
    for (int h = 0; h < 64; ++h) {
        float a[4], bv[4];
        #pragma unroll
        for (int m = 0; m < 4; ++m) a[m] = As[h][ty * 4 + m];
        #pragma unroll
        for (int n = 0; n < 4; ++n) bv[n] = Ws[h][tx + 16 * n];
        #pragma unroll
        for (int m = 0; m < 4; ++m)
            #pragma unroll
            for (int n = 0; n < 4; ++n) acc[m][n] = fmaf(a[m], bv[n], acc[m][n]);
    }

    #pragma unroll
    for (int n = 0; n < 4; ++n) {
        int o = tx + 16 * n;
        float bo = b2[o];
        #pragma unroll
        for (int m = 0; m < 4; ++m)
            Fout[(size_t)(n0 + ty * 4 + m) * 64 + o] = acc[m][n] + bo;
    }
}

// ---------------- global mean pool over nodes ------------------------------
__global__ void pool_kernel(const float* __restrict__ F) {
    __shared__ float red[4][64];
    int t = threadIdx.x;
    int h = t & 63, s = t >> 6;
    int b = blockIdx.x;
    float acc = 0.f;
    for (int n = s; n < N_; n += 4)
        acc += F[((size_t)b * N_ + n) * H_ + h];
    red[s][h] = acc;
    __syncthreads();
    if (t < 64)
        g_pool[b * H_ + t] = (red[0][t] + red[1][t] + red[2][t] + red[3][t]) * (1.f / N_);
}

// ---------------- FC head (also resets BN accumulators for next replay) ----
__global__ void fc_kernel(const float* __restrict__ wf1, const float* __restrict__ bf1,
                          const float* __restrict__ gf,  const float* __restrict__ bef,
                          const float* __restrict__ wf2, const float* __restrict__ bf2,
                          float* __restrict__ out) {
    __shared__ float zs[32][33];
    __shared__ float sc[32], sh[32];
    int t = threadIdx.x;
    int b = t >> 5, j = t & 31;

    if (t < 256) { g_sum[t] = 0.f; g_sqs[t] = 0.f; }   // restore zero-init state

    float acc = bf1[j];
    #pragma unroll
    for (int h = 0; h < 64; ++h)
        acc = fmaf(g_pool[b * 64 + h], wf1[h * 32 + j], acc);
    zs[b][j] = acc;
    __syncthreads();

    if (t < 32) {
        float s = 0.f;
        for (int q = 0; q < 32; ++q) s += zs[q][t];
        float m = s * (1.f / 32.f);
        float v = 0.f;
        for (int q = 0; q < 32; ++q) { float d = zs[q][t] - m; v = fmaf(d, d, v); }
        v *= (1.f / 32.f);
        float s2 = gf[t] * rsqrtf(v + 1e-5f);
        sc[t] = s2;
        sh[t] = fmaf(-m, s2, bef[t]);
    }
    __syncthreads();

    float r = fmaxf(fmaf(zs[b][j], sc[j], sh[j]), 0.f);
    zs[b][j] = r;
    __syncthreads();

    if (t < 64) {
        int q = t >> 1, o = t & 1;
        float a = bf2[o];
        #pragma unroll
        for (int jj = 0; jj < 32; ++jj)
            a = fmaf(zs[q][jj], wf2[jj * 2 + o], a);
        out[q * 2 + o] = a;
    }
}

// ---------------- host ------------------------------------------------------
static void run_layer64(int L, const float* Fin, float* Fout,
                        const float* W1, const float* b1,
                        const float* g, const float* be,
                        const float* W2, const float* b2) {
    d2_kernel<64><<<4096, 256>>>(Fin);
    dist64_kernel<<<dim3(36, 1, 32), 256>>>(Fin);
    pq64_kernel<<<256, 256>>>(Fin, W1, b1);
    topk64_kernel<<<4096, 256>>>(L);
    bn_mlp2_kernel<<<512, 256>>>(Fout, W2, b2, g, be, L);
}

extern "C" void kernel_launch(void* const* d_in, const int* in_sizes, int n_in,
                              void* d_out, int out_size) {
    const float* x   = (const float*)d_in[0];
    const float* w0a = (const float*)d_in[1];
    const float* b0a = (const float*)d_in[2];
    const float* g0  = (const float*)d_in[3];
    const float* be0 = (const float*)d_in[4];
    const float* w0b = (const float*)d_in[5];
    const float* b0b = (const float*)d_in[6];
    const float* wa  = (const float*)d_in[7];
    const float* ba  = (const float*)d_in[8];
    const float* ga  = (const float*)d_in[9];
    const float* bea = (const float*)d_in[10];
    const float* wb  = (const float*)d_in[11];
    const float* bb  = (const float*)d_in[12];
    const float* wf1 = (const float*)d_in[13];
    const float* bf1 = (const float*)d_in[14];
    const float* gf  = (const float*)d_in[15];
    const float* bef = (const float*)d_in[16];
    const float* wf2 = (const float*)d_in[17];
    const float* bf2 = (const float*)d_in[18];
    float* out = (float*)d_out;

    float *f0 = nullptr, *f1 = nullptr;
    cudaGetSymbolAddress((void**)&f0, g_f0);
    cudaGetSymbolAddress((void**)&f1, g_f1);

    // ---- layer 0 (CIN=3): fused dist+topk, no g_dist traffic ----
    d2_kernel<3><<<4096, 256>>>(x);
    pq3_kernel<<<8192, 256>>>(x, w0a, b0a);
    topk3_kernel<<<4096, 256>>>(x);
    bn_mlp2_kernel<<<512, 256>>>(f0, w0b, b0b, g0, be0, 0);

    // ---- layers 1..3 (CIN=64) ----
    run_layer64(1, f0, f1, wa,            ba,       ga,       bea,       wb,            bb);
    run_layer64(2, f1, f0, wa + 128 * 64, ba + 64,  ga + 64,  bea + 64,  wb + 64 * 64,  bb + 64);
    run_layer64(3, f0, f1, wa + 256 * 64, ba + 128, ga + 128, bea + 128, wb + 128 * 64, bb + 128);

    pool_kernel<<<32, 256>>>(f1);
    fc_kernel<<<1, 1024>>>(wf1, bf1, gf, bef, wf2, bf2, out);
}

// round 15
// speedup vs baseline: 1.4445x; 1.0006x over previous
#include <cuda_runtime.h>
#include <cstdint>

#define B_  32
#define N_  1024
#define K_  12
#define H_  64
#define BN_ (B_ * N_)        // 32768 nodes
#define ME_ (BN_ * K_)       // 393216 edges

// ---------------- scratch (static; no cudaMalloc) --------------------------
__device__ float g_dist[(size_t)B_ * N_ * N_];   // 128 MB (CIN=64 layers only)
__device__ int   g_idx[ME_];
__device__ float g_d2[BN_];
__device__ float g_R[(size_t)BN_ * H_];          // P - Q + b1
__device__ float g_Q[(size_t)BN_ * H_];
__device__ float g_f0[(size_t)BN_ * H_];
__device__ float g_f1[(size_t)BN_ * H_];
__device__ float g_sum[4 * H_];                  // per-layer; zero-init; fc restores 0
__device__ float g_sqs[4 * H_];
__device__ float g_pool[B_ * H_];

__device__ __forceinline__ float f4c(const float4& v, int i) {
    return i == 0 ? v.x : i == 1 ? v.y : i == 2 ? v.z : v.w;
}

// ---------------- squared norms --------------------------------------------
template<int CIN>
__global__ void d2_kernel(const float* __restrict__ F) {
    int w    = (blockIdx.x * blockDim.x + threadIdx.x) >> 5;
    int lane = threadIdx.x & 31;
    const float* row = F + (size_t)w * CIN;
    float s = 0.f;
    for (int c = lane; c < CIN; c += 32) { float v = row[c]; s = fmaf(v, v, s); }
    #pragma unroll
    for (int o = 16; o; o >>= 1) s += __shfl_down_sync(0xffffffffu, s, o);
    if (lane == 0) g_d2[w] = s;
}

// ---------------- pairwise distances, CIN=64, SYMMETRIC tile pairs ----------
__global__ __launch_bounds__(256) void dist64_kernel(const float* __restrict__ F) {
    __shared__ __align__(16) float Xi[128][36];
    __shared__ __align__(16) float Xj[128][36];
    __shared__ float d2i[128], d2j[128];

    int tx = threadIdx.x & 15, ty = threadIdx.x >> 4;
    int t  = threadIdx.x;
    int b  = blockIdx.z;

    // pair id -> (ti, tj), ti <= tj
    int p = blockIdx.x;
    int ti = 0;
    while (p >= 8 - ti) { p -= 8 - ti; ++ti; }
    int tj = ti + p;

    int i0 = ti * 128, j0 = tj * 128;
    const float* Fb = F + (size_t)b * (N_ * 64);

    if (t < 128) { d2i[t] = g_d2[b * N_ + i0 + t]; d2j[t] = g_d2[b * N_ + j0 + t]; }

    float acc[8][8];
    #pragma unroll
    for (int m = 0; m < 8; ++m)
        #pragma unroll
        for (int n = 0; n < 8; ++n) acc[m][n] = 0.f;

    for (int c0 = 0; c0 < 64; c0 += 32) {
        __syncthreads();
        for (int i = t; i < 128 * 32; i += 256) {
            int r = i >> 5, k = i & 31;
            Xi[r][k] = Fb[(size_t)(i0 + r) * 64 + c0 + k];
            Xj[r][k] = Fb[(size_t)(j0 + r) * 64 + c0 + k];
        }
        __syncthreads();
        #pragma unroll
        for (int k = 0; k < 32; k += 4) {
            float4 b4[8];
            #pragma unroll
            for (int n = 0; n < 8; ++n)
                b4[n] = *(const float4*)&Xj[tx + 16 * n][k];
            #pragma unroll
            for (int m = 0; m < 8; ++m) {
                float4 a4 = *(const float4*)&Xi[ty * 8 + m][k];
                #pragma unroll
                for (int kk = 0; kk < 4; ++kk) {
                    float av = f4c(a4, kk);
                    #pragma unroll
                    for (int n = 0; n < 8; ++n)
                        acc[m][n] = fmaf(av, f4c(b4[n], kk), acc[m][n]);
                }
            }
        }
    }

    // direct tile: rows i, cols j
    float* D = g_dist + ((size_t)b * N_ + i0) * N_ + j0;
    #pragma unroll
    for (int m = 0; m < 8; ++m) {
        int r = ty * 8 + m;
        float di = d2i[r];
        #pragma unroll
        for (int n = 0; n < 8; ++n)
            D[(size_t)r * N_ + tx + 16 * n] = di + d2j[tx + 16 * n] - 2.0f * acc[m][n];
    }

    // mirrored tile: rows j, cols i (bit-identical values)
    if (ti != tj) {
        float* DT = g_dist + ((size_t)b * N_ + j0) * N_ + i0;
        #pragma unroll
        for (int n = 0; n < 8; ++n) {
            int jr = tx + 16 * n;
            float dj = d2j[jr];
            float4 o0, o1;
            o0.x = dj + d2i[ty * 8 + 0] - 2.0f * acc[0][n];
            o0.y = dj + d2i[ty * 8 + 1] - 2.0f * acc[1][n];
            o0.z = dj + d2i[ty * 8 + 2] - 2.0f * acc[2][n];
            o0.w = dj + d2i[ty * 8 + 3] - 2.0f * acc[3][n];
            o1.x = dj + d2i[ty * 8 + 4] - 2.0f * acc[4][n];
            o1.y = dj + d2i[ty * 8 + 5] - 2.0f * acc[5][n];
            o1.z = dj + d2i[ty * 8 + 6] - 2.0f * acc[6][n];
            o1.w = dj + d2i[ty * 8 + 7] - 2.0f * acc[7][n];
            *(float4*)&DT[(size_t)jr * N_ + ty * 8]     = o0;
            *(float4*)&DT[(size_t)jr * N_ + ty * 8 + 4] = o1;
        }
    }
}

// ---------------- top-K machinery (round-11 proven: shfl butterflies) -------
__device__ __forceinline__ unsigned fkey(float d) {
    unsigned u = __float_as_uint(d);
    return u ^ (((unsigned)((int)u >> 31)) | 0x80000000u);
}

__device__ __forceinline__ void ins12(unsigned* lst, unsigned k) {
    if (k < lst[11]) {
        unsigned cur = k;
        #pragma unroll
        for (int s = 0; s < 12; ++s) {
            unsigned lo = min(lst[s], cur);
            cur = max(lst[s], cur);
            lst[s] = lo;
        }
    }
}

__device__ __forceinline__ unsigned warp_thresh12(unsigned* lst, int lane) {
    unsigned T = 0;
    #pragma unroll 1
    for (int r = 0; r < 12; ++r) {
        unsigned w = lst[0];
        #pragma unroll
        for (int o = 16; o; o >>= 1) w = min(w, __shfl_xor_sync(0xffffffffu, w, o));
        unsigned mask = __ballot_sync(0xffffffffu, lst[0] == w);
        if (lane == __ffs(mask) - 1) {
            #pragma unroll
            for (int s = 0; s < 11; ++s) lst[s] = lst[s + 1];
            lst[11] = 0xFFFFFFFFu;
        }
        T = w;
    }
    return T;
}

// Exact 12th-smallest of the warp's 32 keys-per-lane using the order-stat
// bound: m12 (12th smallest of the 32 per-lane minima) >= T12.
__device__ __forceinline__ unsigned warp_t12(const unsigned* keys, unsigned kmin,
                                             int lane, unsigned* candw) {
    unsigned m12 = 0;
    {
        unsigned v = kmin;
        #pragma unroll 1
        for (int r = 0; r < 12; ++r) {
            unsigned wv = v;
            #pragma unroll
            for (int o = 16; o; o >>= 1) wv = min(wv, __shfl_xor_sync(0xffffffffu, wv, o));
            m12 = wv;
            unsigned msk = __ballot_sync(0xffffffffu, v == wv);
            if (lane == __ffs(msk) - 1) v = 0xFFFFFFFFu;
        }
    }

    int nc = 0;
    #pragma unroll
    for (int p = 0; p < 32; ++p) nc += (keys[p] <= m12);
    int inc = nc;
    #pragma unroll
    for (int o = 1; o < 32; o <<= 1) {
        int y = __shfl_up_sync(0xffffffffu, inc, o);
        if (lane >= o) inc += y;
    }
    int C   = __shfl_sync(0xffffffffu, inc, 31);
    int off = inc - nc;

    unsigned T = 0;
    if (C <= 64) {
        #pragma unroll
        for (int p = 0; p < 32; ++p)
            if (keys[p] <= m12) candw[off++] = keys[p];
        __syncwarp();
        unsigned v1 = (lane      < C) ? candw[lane]      : 0xFFFFFFFFu;
        unsigned v2 = (lane + 32 < C) ? candw[lane + 32] : 0xFFFFFFFFu;
        #pragma unroll 1
        for (int r = 0; r < 12; ++r) {
            unsigned mv = min(v1, v2);
            #pragma unroll
            for (int o = 16; o; o >>= 1) mv = min(mv, __shfl_xor_sync(0xffffffffu, mv, o));
            T = mv;
            unsigned m1 = __ballot_sync(0xffffffffu, v1 == mv);
            if (m1) {
                if (lane == __ffs(m1) - 1) v1 = 0xFFFFFFFFu;
            } else {
                unsigned m2 = __ballot_sync(0xffffffffu, v2 == mv);
                if (lane == __ffs(m2) - 1) v2 = 0xFFFFFFFFu;
            }
        }
    } else {
        unsigned lst[12];
        #pragma unroll
        for (int i = 0; i < 12; ++i) lst[i] = 0xFFFFFFFFu;
        #pragma unroll
        for (int p = 0; p < 32; ++p) ins12(lst, keys[p]);
        T = warp_thresh12(lst, lane);
    }
    return T;
}

// MODE 0: p=(it*4+c), j=(p>>2)*128 + lane*4 + (p&3)   (float4 strided rows)
// MODE 1: p=it,        j=p*32 + lane
template<int MODE>
__device__ __forceinline__ int map_j(int p, int lane) {
    return (MODE == 0) ? ((p >> 2) * 128 + lane * 4 + (p & 3)) : (p * 32 + lane);
}

// From per-lane less/equal masks, write the exact top-12 index set to sidx[12].
template<int MODE>
__device__ __forceinline__ void select12(unsigned lessm, unsigned eqm,
                                         int lane, int* sidx) {
    int lcnt = __popc(lessm);
    int inc = lcnt;
    #pragma unroll
    for (int o = 1; o < 32; o <<= 1) {
        int y = __shfl_up_sync(0xffffffffu, inc, o);
        if (lane >= o) inc += y;
    }
    int total_less = __shfl_sync(0xffffffffu, inc, 31);   // <= 11
    int r = inc - lcnt;
    unsigned m = lessm;
    while (m) {
        int p = __ffs(m) - 1; m &= m - 1;
        sidx[r++] = map_j<MODE>(p, lane);
    }
    int need = 12 - total_less;
    #pragma unroll 1
    for (int f = 0; f < need; ++f) {
        int jc = eqm ? map_j<MODE>(__ffs(eqm) - 1, lane) : 0x7FFFFFFF;
        int jw = jc;
        #pragma unroll
        for (int o = 16; o; o >>= 1) jw = min(jw, __shfl_xor_sync(0xffffffffu, jw, o));
        if (jc == jw) eqm &= eqm - 1;     // j unique across (p,lane): one lane pops
        if (lane == 0) sidx[total_less + f] = jw;
    }
}

// BN stats: accumulate sum/sumsq of h1 = R[i]+Q[j] for this row's 12 edges.
__device__ __forceinline__ void stats_epilogue(int gi, int gbase, int keep, int lane,
                                               float* ssum, float* ssqs) {
    int h = lane * 2;
    float2 r2 = *(const float2*)&g_R[(size_t)gi * 64 + h];
    float s0 = 0.f, s1 = 0.f, q0 = 0.f, q1 = 0.f;
    #pragma unroll
    for (int k = 0; k < 12; ++k) {
        int j = gbase + __shfl_sync(0xffffffffu, keep, k);
        float2 qv = *(const float2*)&g_Q[(size_t)j * 64 + h];
        float v0 = r2.x + qv.x, v1 = r2.y + qv.y;
        s0 += v0; s1 += v1;
        q0 = fmaf(v0, v0, q0); q1 = fmaf(v1, v1, q1);
    }
    atomicAdd(&ssum[h],     s0);
    atomicAdd(&ssum[h + 1], s1);
    atomicAdd(&ssqs[h],     q0);
    atomicAdd(&ssqs[h + 1], q1);
}

// ---------------- top-K for CIN=64 layers (reads g_dist) + fused BN stats --
__global__ __launch_bounds__(256) void topk64_kernel(int L) {
    __shared__ float ssum[64], ssqs[64];
    __shared__ int   sidx[8][12];
    __shared__ unsigned cand[8][64];
    int t = threadIdx.x;
    if (t < 64) { ssum[t] = 0.f; ssqs[t] = 0.f; }
    __syncthreads();

    int w = t >> 5, lane = t & 31;
    int row = blockIdx.x * 8 + w;
    const float* dr = g_dist + (size_t)row * N_;

    unsigned keys[32];
    unsigned kmin = 0xFFFFFFFFu;
    #pragma unroll
    for (int it = 0; it < 8; ++it) {
        float4 dv = *(const float4*)(dr + it * 128 + lane * 4);
        keys[it * 4 + 0] = fkey(dv.x);
        keys[it * 4 + 1] = fkey(dv.y);
        keys[it * 4 + 2] = fkey(dv.z);
        keys[it * 4 + 3] = fkey(dv.w);
        kmin = min(kmin, min(min(keys[it * 4], keys[it * 4 + 1]),
                             min(keys[it * 4 + 2], keys[it * 4 + 3])));
    }

    unsigned T = warp_t12(keys, kmin, lane, cand[w]);

    unsigned lessm = 0, eqm = 0;
    #pragma unroll
    for (int p = 0; p < 32; ++p) {
        lessm |= (unsigned)(keys[p] < T)  << p;
        eqm   |= (unsigned)(keys[p] == T) << p;
    }
    select12<0>(lessm, eqm, lane, sidx[w]);
    __syncwarp();

    int keep = sidx[w][lane < 12 ? lane : 0];
    if (lane < 12) g_idx[row * 12 + lane] = keep;
    stats_epilogue(row, (row >> 10) << 10, keep, lane, ssum, ssqs);
    __syncthreads();
    if (t < 64) { atomicAdd(&g_sum[L * 64 + t], ssum[t]); atomicAdd(&g_sqs[L * 64 + t], ssqs[t]); }
}

// ---------------- fused dist+top-K for layer 0 (CIN=3) + BN stats ----------
__global__ __launch_bounds__(256) void topk3_kernel(const float* __restrict__ x) {
    __shared__ float xs[3072];
    __shared__ float sd2[1024];
    __shared__ float ssum[64], ssqs[64];
    __shared__ int   sidx[8][12];
    __shared__ unsigned cand[8][64];

    int t = threadIdx.x;
    int b = blockIdx.x >> 7;
    int rbase = (blockIdx.x & 127) * 8;
    const float* xb = x + b * 3072;

    for (int i = t; i < 3072; i += 256) xs[i] = xb[i];
    for (int i = t; i < 1024; i += 256) sd2[i] = g_d2[b * 1024 + i];
    if (t < 64) { ssum[t] = 0.f; ssqs[t] = 0.f; }
    __syncthreads();

    int w = t >> 5, lane = t & 31;
    int il = rbase + w;
    float xi0 = xs[il * 3], xi1 = xs[il * 3 + 1], xi2 = xs[il * 3 + 2];
    float d2iv = sd2[il];

    unsigned keys[32];
    unsigned kmin = 0xFFFFFFFFu;
    #pragma unroll
    for (int it = 0; it < 32; ++it) {
        int j = it * 32 + lane;
        float a = fmaf(xi0, xs[j * 3], 0.f);
        a = fmaf(xi1, xs[j * 3 + 1], a);
        a = fmaf(xi2, xs[j * 3 + 2], a);
        float d = d2iv + sd2[j] - 2.0f * a;
        keys[it] = fkey(d);
        kmin = min(kmin, keys[it]);
    }

    unsigned T = warp_t12(keys, kmin, lane, cand[w]);

    unsigned lessm = 0, eqm = 0;
    #pragma unroll
    for (int it = 0; it < 32; ++it) {
        lessm |= (unsigned)(keys[it] < T)  << it;
        eqm   |= (unsigned)(keys[it] == T) << it;
    }
    select12<1>(lessm, eqm, lane, sidx[w]);
    __syncwarp();

    int gi = b * 1024 + il;
    int keep = sidx[w][lane < 12 ? lane : 0];
    if (lane < 12) g_idx[gi * 12 + lane] = keep;
    stats_epilogue(gi, b << 10, keep, lane, ssum, ssqs);
    __syncthreads();
    if (t < 64) { atomicAdd(&g_sum[t], ssum[t]); atomicAdd(&g_sqs[t], ssqs[t]); }
}

// ---------------- node-level MLP1 decomposition ----------------------------
__global__ __launch_bounds__(256) void pq64_kernel(const float* __restrict__ F,
                                                   const float* __restrict__ W1,
                                                   const float* __restrict__ b1) {
    __shared__ __align__(16) float Xs[128][36];
    __shared__ __align__(16) float Wt[128][36];
    int tx = threadIdx.x & 15, ty = threadIdx.x >> 4;
    int t  = threadIdx.x;
    int n0 = blockIdx.x * 128;

    float acc[8][8];
    #pragma unroll
    for (int m = 0; m < 8; ++m)
        #pragma unroll
        for (int n = 0; n < 8; ++n) acc[m][n] = 0.f;

    for (int c0 = 0; c0 < 64; c0 += 32) {
        __syncthreads();
        for (int i = t; i < 128 * 32; i += 256) {
            int r = i >> 5, k = i & 31;
            Xs[r][k] = F[(size_t)(n0 + r) * 64 + c0 + k];
            Wt[r][k] = W1[(c0 + k + ((r >> 6) << 6)) * 64 + (r & 63)];
        }
        __syncthreads();
        #pragma unroll
        for (int k = 0; k < 32; k += 4) {
            float4 b4[8];
            #pragma unroll
            for (int n = 0; n < 8; ++n)
                b4[n] = *(const float4*)&Wt[tx + 16 * n][k];
            #pragma unroll
            for (int m = 0; m < 8; ++m) {
                float4 a4 = *(const float4*)&Xs[ty * 8 + m][k];
                #pragma unroll
                for (int kk = 0; kk < 4; ++kk) {
                    float av = f4c(a4, kk);
                    #pragma unroll
                    for (int n = 0; n < 8; ++n)
                        acc[m][n] = fmaf(av, f4c(b4[n], kk), acc[m][n]);
                }
            }
        }
    }

    #pragma unroll
    for (int m = 0; m < 8; ++m) {
        size_t node = n0 + ty * 8 + m;
        #pragma unroll
        for (int n = 0; n < 4; ++n) {
            int h = tx + 16 * n;
            float P = acc[m][n], Q = acc[m][n + 4];
            g_R[node * 64 + h] = P - Q + b1[h];
            g_Q[node * 64 + h] = Q;
        }
    }
}

__global__ void pq3_kernel(const float* __restrict__ x,
                           const float* __restrict__ W1,
                           const float* __restrict__ b1) {
    int gid = blockIdx.x * 256 + threadIdx.x;    // node*64 + h
    int node = gid >> 6, h = gid & 63;
    const float* xr = x + node * 3;
    float x0 = xr[0], x1 = xr[1], x2 = xr[2];
    float P = fmaf(x0, W1[h],       fmaf(x1, W1[64 + h],  x2 * W1[128 + h]));
    float Q = fmaf(x0, W1[192 + h], fmaf(x1, W1[256 + h], x2 * W1[320 + h]));
    g_R[gid] = P - Q + b1[h];
    g_Q[gid] = Q;
}

// ---------------- BN(scale/shift in-block) + ReLU + mean-K + W2 GEMM -------
__global__ __launch_bounds__(256) void bn_mlp2_kernel(float* __restrict__ Fout,
                                                      const float* __restrict__ W2,
                                                      const float* __restrict__ b2,
                                                      const float* __restrict__ g,
                                                      const float* __restrict__ be,
                                                      int L) {
    __shared__ float As[64][65];
    __shared__ float Ws[64][65];
    __shared__ float ssc[64], ssh[64];
    int t  = threadIdx.x;
    int n0 = blockIdx.x * 64;

    if (t < 64) {
        const float invM = 1.f / (float)ME_;
        float m = g_sum[L * 64 + t] * invM;
        float v = g_sqs[L * 64 + t] * invM - m * m;
        float sc = g[t] * rsqrtf(v + 1e-5f);
        ssc[t] = sc;
        ssh[t] = fmaf(-m, sc, be[t]);
    }
    for (int i = t; i < 64 * 64; i += 256) Ws[i >> 6][i & 63] = W2[i];
    __syncthreads();

    {
        int nloc = t >> 2;
        int node = n0 + nloc;
        int hq   = (t & 3) * 16;
        float R[16], sc[16], sh[16], a[16];
        #pragma unroll
        for (int p = 0; p < 4; ++p)
            *(float4*)&R[p * 4] = *(const float4*)&g_R[(size_t)node * 64 + hq + p * 4];
        #pragma unroll
        for (int r = 0; r < 16; ++r) { sc[r] = ssc[hq + r]; sh[r] = ssh[hq + r]; a[r] = 0.f; }

        // prefetch all 12 neighbor indices (48B row, 16B-aligned)
        const int4* ip4 = (const int4*)(g_idx + node * 12);
        int4 iq0 = ip4[0], iq1 = ip4[1], iq2 = ip4[2];
        int idx[12] = {iq0.x, iq0.y, iq0.z, iq0.w,
                       iq1.x, iq1.y, iq1.z, iq1.w,
                       iq2.x, iq2.y, iq2.z, iq2.w};
        int base = (node >> 10) << 10;

        // unroll-by-2: 8 independent LDG.128 in flight; accumulation order
        // per channel stays k-ascending (bit-identical to the serial loop)
        #pragma unroll
        for (int k = 0; k < 12; k += 2) {
            const float4* Qa = (const float4*)&g_Q[(size_t)(base + idx[k])     * 64 + hq];
            const float4* Qb = (const float4*)&g_Q[(size_t)(base + idx[k + 1]) * 64 + hq];
            float qa[16], qb[16];
            #pragma unroll
            for (int p = 0; p < 4; ++p) *(float4*)&qa[p * 4] = Qa[p];
            #pragma unroll
            for (int p = 0; p < 4; ++p) *(float4*)&qb[p * 4] = Qb[p];
            #pragma unroll
            for (int r = 0; r < 16; ++r)
                a[r] += fmaxf(fmaf(sc[r], R[r] + qa[r], sh[r]), 0.f);
            #pragma unroll
            for (int r = 0; r < 16; ++r)
                a[r] += fmaxf(fmaf(sc[r], R[r] + qb[r], sh[r]), 0.f);
        }
        #pragma unroll
        for (int r = 0; r < 16; ++r) As[hq + r][nloc] = a[r] * (1.f / 12.f);
    }
    __syncthreads();

    int tx = t & 15, ty = t >> 4;
    float acc[4][4];
    #pragma unroll
    for (int m = 0; m < 4; ++m)
        #pragma unroll
        for (int n = 0; n < 4; ++n) acc[m][n] = 0.f;

    #pragma unroll
    for (int h = 0; h < 64; ++h) {
        float a[4], bv[4];
        #pragma unroll
        for (int m = 0; m < 4; ++m) a[m] = As[h][ty * 4 + m];
        #pragma unroll
        for (int n = 0; n < 4; ++n) bv[n] = Ws[h][tx + 16 * n];
        #pragma unroll
        for (int m = 0; m < 4; ++m)
            #pragma unroll
            for (int n = 0; n < 4; ++n) acc[m][n] = fmaf(a[m], bv[n], acc[m][n]);
    }

    #pragma unroll
    for (int n = 0; n < 4; ++n) {
        int o = tx + 16 * n;
        float bo = b2[o];
        #pragma unroll
        for (int m = 0; m < 4; ++m)
            Fout[(size_t)(n0 + ty * 4 + m) * 64 + o] = acc[m][n] + bo;
    }
}

// ---------------- global mean pool over nodes ------------------------------
__global__ void pool_kernel(const float* __restrict__ F) {
    __shared__ float red[4][64];
    int t = threadIdx.x;
    int h = t & 63, s = t >> 6;
    int b = blockIdx.x;
    float acc = 0.f;
    for (int n = s; n < N_; n += 4)
        acc += F[((size_t)b * N_ + n) * H_ + h];
    red[s][h] = acc;
    __syncthreads();
    if (t < 64)
        g_pool[b * H_ + t] = (red[0][t] + red[1][t] + red[2][t] + red[3][t]) * (1.f / N_);
}

// ---------------- FC head (also resets BN accumulators for next replay) ----
__global__ void fc_kernel(const float* __restrict__ wf1, const float* __restrict__ bf1,
                          const float* __restrict__ gf,  const float* __restrict__ bef,
                          const float* __restrict__ wf2, const float* __restrict__ bf2,
                          float* __restrict__ out) {
    __shared__ float zs[32][33];
    __shared__ float sc[32], sh[32];
    int t = threadIdx.x;
    int b = t >> 5, j = t & 31;

    if (t < 256) { g_sum[t] = 0.f; g_sqs[t] = 0.f; }   // restore zero-init state

    float acc = bf1[j];
    #pragma unroll
    for (int h = 0; h < 64; ++h)
        acc = fmaf(g_pool[b * 64 + h], wf1[h * 32 + j], acc);
    zs[b][j] = acc;
    __syncthreads();

    if (t < 32) {
        float s = 0.f;
        for (int q = 0; q < 32; ++q) s += zs[q][t];
        float m = s * (1.f / 32.f);
        float v = 0.f;
        for (int q = 0; q < 32; ++q) { float d = zs[q][t] - m; v = fmaf(d, d, v); }
        v *= (1.f / 32.f);
        float s2 = gf[t] * rsqrtf(v + 1e-5f);
        sc[t] = s2;
        sh[t] = fmaf(-m, s2, bef[t]);
    }
    __syncthreads();

    float r = fmaxf(fmaf(zs[b][j], sc[j], sh[j]), 0.f);
    zs[b][j] = r;
    __syncthreads();

    if (t < 64) {
        int q = t >> 1, o = t & 1;
        float a = bf2[o];
        #pragma unroll
        for (int jj = 0; jj < 32; ++jj)
            a = fmaf(zs[q][jj], wf2[jj * 2 + o], a);
        out[q * 2 + o] = a;
    }
}

// ---------------- host ------------------------------------------------------
static void run_layer64(int L, const float* Fin, float* Fout,
                        const float* W1, const float* b1,
                        const float* g, const float* be,
                        const float* W2, const float* b2) {
    d2_kernel<64><<<4096, 256>>>(Fin);
    dist64_kernel<<<dim3(36, 1, 32), 256>>>(Fin);
    pq64_kernel<<<256, 256>>>(Fin, W1, b1);
    topk64_kernel<<<4096, 256>>>(L);
    bn_mlp2_kernel<<<512, 256>>>(Fout, W2, b2, g, be, L);
}

extern "C" void kernel_launch(void* const* d_in, const int* in_sizes, int n_in,
                              void* d_out, int out_size) {
    const float* x   = (const float*)d_in[0];
    const float* w0a = (const float*)d_in[1];
    const float* b0a = (const float*)d_in[2];
    const float* g0  = (const float*)d_in[3];
    const float* be0 = (const float*)d_in[4];
    const float* w0b = (const float*)d_in[5];
    const float* b0b = (const float*)d_in[6];
    const float* wa  = (const float*)d_in[7];
    const float* ba  = (const float*)d_in[8];
    const float* ga  = (const float*)d_in[9];
    const float* bea = (const float*)d_in[10];
    const float* wb  = (const float*)d_in[11];
    const float* bb  = (const float*)d_in[12];
    const float* wf1 = (const float*)d_in[13];
    const float* bf1 = (const float*)d_in[14];
    const float* gf  = (const float*)d_in[15];
    const float* bef = (const float*)d_in[16];
    const float* wf2 = (const float*)d_in[17];
    const float* bf2 = (const float*)d_in[18];
    float* out = (float*)d_out;

    float *f0 = nullptr, *f1 = nullptr;
    cudaGetSymbolAddress((void**)&f0, g_f0);
    cudaGetSymbolAddress((void**)&f1, g_f1);

    // ---- layer 0 (CIN=3): fused dist+topk, no g_dist traffic ----
    d2_kernel<3><<<4096, 256>>>(x);
    pq3_kernel<<<8192, 256>>>(x, w0a, b0a);
    topk3_kernel<<<4096, 256>>>(x);
    bn_mlp2_kernel<<<512, 256>>>(f0, w0b, b0b, g0, be0, 0);

    // ---- layers 1..3 (CIN=64) ----
    run_layer64(1, f0, f1, wa,            ba,       ga,       bea,       wb,            bb);
    run_layer64(2, f1, f0, wa + 128 * 64, ba + 64,  ga + 64,  bea + 64,  wb + 64 * 64,  bb + 64);
    run_layer64(3, f0, f1, wa + 256 * 64, ba + 128, ga + 128, bea + 128, wb + 128 * 64, bb + 128);

    pool_kernel<<<32, 256>>>(f1);
    fc_kernel<<<1, 1024>>>(wf1, bf1, gf, bef, wf2, bf2, out);
}